// round 3
// baseline (speedup 1.0000x reference)
#include <cuda_runtime.h>
#include <cstdint>
#include <math.h>

#define NN 50000
#define EE 600000
#define DD 128
#define GG 128

// ---------------- device scratch (no allocations allowed) ----------------
__device__ float g_xa[NN * DD];       // aggregation output
__device__ float g_y0[NN * DD];       // layer output ping
__device__ float g_y1[NN * DD];       // layer output pong
__device__ int   g_deg[NN];
__device__ int   g_fill[NN];
__device__ float g_dinv[NN];
__device__ int   g_rowptr[NN + 1];
__device__ int   g_csrc[EE];
__device__ float g_cw[EE];

__device__ __forceinline__ uint32_t f2tf32(float f) {
    uint32_t r;
    asm("cvt.rna.tf32.f32 %0, %1;" : "=r"(r) : "f"(f));
    return r;
}

__device__ __forceinline__ void mma_tf32(float c[4], const uint32_t a[4], const uint32_t b[2]) {
    asm volatile(
        "mma.sync.aligned.m16n8k8.row.col.f32.tf32.tf32.f32 "
        "{%0,%1,%2,%3}, {%4,%5,%6,%7}, {%8,%9}, {%0,%1,%2,%3};"
        : "+f"(c[0]), "+f"(c[1]), "+f"(c[2]), "+f"(c[3])
        : "r"(a[0]), "r"(a[1]), "r"(a[2]), "r"(a[3]), "r"(b[0]), "r"(b[1]));
}

// ======================= CSR build =======================
__global__ void k_init() {
    int i = blockIdx.x * blockDim.x + threadIdx.x;
    if (i < NN) { g_deg[i] = 0; g_fill[i] = 0; }
}
__global__ void k_deg(const int* __restrict__ ei) {
    int e = blockIdx.x * blockDim.x + threadIdx.x;
    if (e < EE) atomicAdd(&g_deg[ei[EE + e]], 1);
}
__global__ void k_scan() {
    const int CH = (NN + 1023) / 1024;
    __shared__ int ss[1024];
    int t = threadIdx.x;
    int vals[CH];
    int base = t * CH;
    int loc = 0;
#pragma unroll
    for (int i = 0; i < CH; ++i) {
        int idx = base + i;
        int v = (idx < NN) ? g_deg[idx] : 0;
        vals[i] = loc;
        loc += v;
    }
    ss[t] = loc;
    __syncthreads();
    for (int off = 1; off < 1024; off <<= 1) {
        int v = (t >= off) ? ss[t - off] : 0;
        __syncthreads();
        ss[t] += v;
        __syncthreads();
    }
    int pre = (t > 0) ? ss[t - 1] : 0;
#pragma unroll
    for (int i = 0; i < CH; ++i) {
        int idx = base + i;
        if (idx < NN) g_rowptr[idx] = pre + vals[i];
    }
    if (t == 1023) g_rowptr[NN] = ss[1023];
}
__global__ void k_dinv() {
    int i = blockIdx.x * blockDim.x + threadIdx.x;
    if (i < NN) g_dinv[i] = rsqrtf((float)(g_deg[i] + 1));
}
__global__ void k_fill(const int* __restrict__ ei) {
    int e = blockIdx.x * blockDim.x + threadIdx.x;
    if (e < EE) {
        int s = ei[e];
        int d = ei[EE + e];
        int pos = g_rowptr[d] + atomicAdd(&g_fill[d], 1);
        g_csrc[pos] = s;
        g_cw[pos] = g_dinv[s] * g_dinv[d];
    }
}

// ======================= aggregation: xa = A_norm @ x =======================
__global__ void __launch_bounds__(256) k_agg(const float* __restrict__ xin,
                                             float* __restrict__ y) {
    int w = (blockIdx.x * blockDim.x + threadIdx.x) >> 5;
    int lane = threadIdx.x & 31;
    if (w >= NN) return;
    int col = lane * 4;

    float di = g_dinv[w];
    float sw = di * di;
    float4 acc = *(const float4*)(xin + (size_t)w * DD + col);
    acc.x *= sw; acc.y *= sw; acc.z *= sw; acc.w *= sw;

    int e0 = g_rowptr[w], e1 = g_rowptr[w + 1];
    for (int e = e0; e < e1; ++e) {
        int s = __ldg(&g_csrc[e]);
        float wt = __ldg(&g_cw[e]);
        float4 hs = *(const float4*)(xin + (size_t)s * DD + col);
        acc.x += wt * hs.x; acc.y += wt * hs.y;
        acc.z += wt * hs.z; acc.w += wt * hs.w;
    }
    *(float4*)(y + (size_t)w * DD + col) = acc;
}

// ======================= fused tf32 mma.sync GEMM + epilogue =======================
// y = SiLU( LN(A @ W + b)*g + be + xres ), one CTA per 128-row tile.
// 8 warps, 4(m) x 2(n); warp tile 32x64 = 2x8 fragments of m16n8k8.
#define TILE_M 128
#define SST 132                 // smem row stride (floats), pad for banks
#define DYN_SMEM (2 * 128 * SST * 4)

__global__ void __launch_bounds__(256) k_gemm_fused(
    const float* __restrict__ A, const float* __restrict__ Wm,
    const float* __restrict__ bias, const float* __restrict__ gamma,
    const float* __restrict__ beta, const float* __restrict__ xres,
    float* __restrict__ y) {
    extern __shared__ float smem[];
    float* As = smem;                 // [128][SST] tf32 bits; reused for C
    float* Bs = smem + 128 * SST;     // [n][k] tf32 bits
    uint32_t* Asu = (uint32_t*)As;
    uint32_t* Bsu = (uint32_t*)Bs;
    __shared__ float s_b[128], s_g[128], s_be[128];

    int tid = threadIdx.x;
    int wid = tid >> 5;
    int lane = tid & 31;
    int m0 = blockIdx.x * TILE_M;

    if (tid < 128) { s_b[tid] = bias[tid]; s_g[tid] = gamma[tid]; s_be[tid] = beta[tid]; }

    // load A tile [128 rows][128 cols] as tf32, row-major stride SST
    for (int i = tid; i < 128 * 32; i += 256) {
        int m = i >> 5;
        int c = (i & 31) << 2;
        int gm = m0 + m;
        float4 v = (gm < NN) ? *(const float4*)(A + (size_t)gm * 128 + c)
                             : make_float4(0.f, 0.f, 0.f, 0.f);
        uint4 t = make_uint4(f2tf32(v.x), f2tf32(v.y), f2tf32(v.z), f2tf32(v.w));
        *(uint4*)&Asu[m * SST + c] = t;
    }
    // load B as Bs[n][k] = W[k][n] (transposed), lanes walk k -> conflict-free stores
    for (int i = tid; i < 128 * 128; i += 256) {
        int k = i & 127;
        int n = i >> 7;
        Bsu[n * SST + k] = f2tf32(Wm[(size_t)k * 128 + n]);
    }
    __syncthreads();

    const int wm = (wid >> 1) * 32;
    const int wn = (wid & 1) * 64;
    const int qrow = lane >> 2;     // 0..7
    const int qcol = lane & 3;      // 0..3

    float c[2][8][4];
#pragma unroll
    for (int mt = 0; mt < 2; ++mt)
#pragma unroll
        for (int nt = 0; nt < 8; ++nt)
#pragma unroll
            for (int j = 0; j < 4; ++j) c[mt][nt][j] = 0.f;

#pragma unroll
    for (int ks = 0; ks < 16; ++ks) {
        int k0 = ks * 8;
        uint32_t a[2][4], b[8][2];
#pragma unroll
        for (int mt = 0; mt < 2; ++mt) {
            int r = wm + mt * 16 + qrow;
            a[mt][0] = Asu[r * SST + k0 + qcol];
            a[mt][1] = Asu[(r + 8) * SST + k0 + qcol];
            a[mt][2] = Asu[r * SST + k0 + qcol + 4];
            a[mt][3] = Asu[(r + 8) * SST + k0 + qcol + 4];
        }
#pragma unroll
        for (int nt = 0; nt < 8; ++nt) {
            int n = wn + nt * 8 + qrow;
            b[nt][0] = Bsu[n * SST + k0 + qcol];
            b[nt][1] = Bsu[n * SST + k0 + qcol + 4];
        }
#pragma unroll
        for (int mt = 0; mt < 2; ++mt)
#pragma unroll
            for (int nt = 0; nt < 8; ++nt)
                mma_tf32(c[mt][nt], a[mt], b[nt]);
    }

    // write C into As (reuse)
    __syncthreads();
#pragma unroll
    for (int mt = 0; mt < 2; ++mt) {
        int r = wm + mt * 16 + qrow;
#pragma unroll
        for (int nt = 0; nt < 8; ++nt) {
            int cc = wn + nt * 8 + qcol * 2;
            *(float2*)&As[r * SST + cc] = make_float2(c[mt][nt][0], c[mt][nt][1]);
            *(float2*)&As[(r + 8) * SST + cc] = make_float2(c[mt][nt][2], c[mt][nt][3]);
        }
    }
    __syncthreads();

    // epilogue: 16 rows per warp; lane holds 4 features
    int colb = lane * 4;
    float4 bv = *(const float4*)(s_b + colb);
    float4 gv = *(const float4*)(s_g + colb);
    float4 bev = *(const float4*)(s_be + colb);
    for (int rr = 0; rr < 16; ++rr) {
        int r = wid * 16 + rr;
        int row = m0 + r;
        if (row >= NN) break;
        float4 d = *(const float4*)&As[r * SST + colb];
        d.x += bv.x; d.y += bv.y; d.z += bv.z; d.w += bv.w;
        float s1 = d.x + d.y + d.z + d.w;
#pragma unroll
        for (int o = 16; o; o >>= 1) s1 += __shfl_xor_sync(0xffffffffu, s1, o);
        float mu = s1 * (1.f / 128.f);
        float d0 = d.x - mu, d1 = d.y - mu, d2 = d.z - mu, d3 = d.w - mu;
        float s2 = d0 * d0 + d1 * d1 + d2 * d2 + d3 * d3;
#pragma unroll
        for (int o = 16; o; o >>= 1) s2 += __shfl_xor_sync(0xffffffffu, s2, o);
        float rs = rsqrtf(s2 * (1.f / 128.f) + 1e-5f);

        float4 xv = *(const float4*)(xres + (size_t)row * 128 + colb);
        float v0 = d0 * rs * gv.x + bev.x + xv.x;
        float v1 = d1 * rs * gv.y + bev.y + xv.y;
        float v2 = d2 * rs * gv.z + bev.z + xv.z;
        float v3 = d3 * rs * gv.w + bev.w + xv.w;
        v0 = v0 / (1.f + __expf(-v0));
        v1 = v1 / (1.f + __expf(-v1));
        v2 = v2 / (1.f + __expf(-v2));
        v3 = v3 / (1.f + __expf(-v3));
        *(float4*)(y + (size_t)row * 128 + colb) = make_float4(v0, v1, v2, v3);
    }
}

// ======================= global mean pool =======================
__device__ __forceinline__ int lowerb(const int* __restrict__ a, int n, int key) {
    int lo = 0, hi = n;
    while (lo < hi) {
        int mid = (lo + hi) >> 1;
        if (a[mid] < key) lo = mid + 1; else hi = mid;
    }
    return lo;
}
__global__ void __launch_bounds__(128) k_pool(const float* __restrict__ x,
                                              const int* __restrict__ batch,
                                              float* __restrict__ out) {
    __shared__ int sl, sh;
    int g = blockIdx.x;
    if (threadIdx.x == 0) {
        sl = lowerb(batch, NN, g);
        sh = lowerb(batch, NN, g + 1);
    }
    __syncthreads();
    int lo = sl, hi = sh;
    int c = threadIdx.x;
    float sum = 0.f;
    for (int n = lo; n < hi; ++n) sum += x[(size_t)n * DD + c];
    out[g * DD + c] = sum / fmaxf((float)(hi - lo), 1.f);
}

// ======================= launch =======================
extern "C" void kernel_launch(void* const* d_in, const int* in_sizes, int n_in,
                              void* d_out, int out_size) {
    const float* x     = (const float*)d_in[0];
    const int*   ei    = (const int*)d_in[1];
    const int*   batch = (const int*)d_in[2];
    const float* W[3]  = {(const float*)d_in[3],  (const float*)d_in[7],  (const float*)d_in[11]};
    const float* b[3]  = {(const float*)d_in[4],  (const float*)d_in[8],  (const float*)d_in[12]};
    const float* g[3]  = {(const float*)d_in[5],  (const float*)d_in[9],  (const float*)d_in[13]};
    const float* be[3] = {(const float*)d_in[6],  (const float*)d_in[10], (const float*)d_in[14]};
    float* out = (float*)d_out;

    float *xa = nullptr, *y0 = nullptr, *y1 = nullptr;
    cudaGetSymbolAddress((void**)&xa, g_xa);
    cudaGetSymbolAddress((void**)&y0, g_y0);
    cudaGetSymbolAddress((void**)&y1, g_y1);

    cudaFuncSetAttribute(k_gemm_fused, cudaFuncAttributeMaxDynamicSharedMemorySize, DYN_SMEM);

    k_init<<<(NN + 255) / 256, 256>>>();
    k_deg<<<(EE + 255) / 256, 256>>>(ei);
    k_scan<<<1, 1024>>>();
    k_dinv<<<(NN + 255) / 256, 256>>>();
    k_fill<<<(EE + 255) / 256, 256>>>(ei);

    const int agg_blocks = (NN * 32 + 255) / 256;
    const int gemm_blocks = (NN + TILE_M - 1) / TILE_M;

    // layer 0: x -> y0
    k_agg<<<agg_blocks, 256>>>(x, xa);
    k_gemm_fused<<<gemm_blocks, 256, DYN_SMEM>>>(xa, W[0], b[0], g[0], be[0], x, y0);
    // layer 1: y0 -> y1
    k_agg<<<agg_blocks, 256>>>(y0, xa);
    k_gemm_fused<<<gemm_blocks, 256, DYN_SMEM>>>(xa, W[1], b[1], g[1], be[1], y0, y1);
    // layer 2: y1 -> y0
    k_agg<<<agg_blocks, 256>>>(y1, xa);
    k_gemm_fused<<<gemm_blocks, 256, DYN_SMEM>>>(xa, W[2], b[2], g[2], be[2], y1, y0);

    k_pool<<<GG, 128>>>(y0, batch, out);
}

// round 4
// speedup vs baseline: 1.1482x; 1.1482x over previous
#include <cuda_runtime.h>
#include <cstdint>
#include <math.h>

#define NN 50000
#define EE 600000
#define DD 128
#define GG 128

// ---------------- device scratch (no allocations allowed) ----------------
__device__ float g_xa[NN * DD];
__device__ float g_y0[NN * DD];
__device__ float g_y1[NN * DD];
__device__ int   g_deg[NN];
__device__ int   g_fill[NN];
__device__ float g_dinv[NN];
__device__ int   g_rowptr[NN + 1];
__device__ int   g_csrc[EE];
__device__ float g_cw[EE];
__device__ uint32_t g_wt[3][DD * DD];   // W^T, tf32 bits, permuted k-layout

__device__ __forceinline__ uint32_t f2tf32(float f) {
    uint32_t r;
    asm("cvt.rna.tf32.f32 %0, %1;" : "=r"(r) : "f"(f));
    return r;
}

__device__ __forceinline__ void mma_tf32(float c[4], const uint32_t a[4], const uint32_t b[2]) {
    asm volatile(
        "mma.sync.aligned.m16n8k8.row.col.f32.tf32.tf32.f32 "
        "{%0,%1,%2,%3}, {%4,%5,%6,%7}, {%8,%9}, {%0,%1,%2,%3};"
        : "+f"(c[0]), "+f"(c[1]), "+f"(c[2]), "+f"(c[3])
        : "r"(a[0]), "r"(a[1]), "r"(a[2]), "r"(a[3]), "r"(b[0]), "r"(b[1]));
}

// permute within 8-col group so (k, k+4) become adjacent: c -> (c&3)*2 + (c>>2)
__device__ __forceinline__ int kperm(int c) { return ((c & 3) << 1) | ((c >> 2) & 1); }

// ======================= CSR build =======================
__global__ void k_init() {
    int i = blockIdx.x * blockDim.x + threadIdx.x;
    if (i < NN) { g_deg[i] = 0; g_fill[i] = 0; }
}
__global__ void k_deg(const int* __restrict__ ei) {
    int e = blockIdx.x * blockDim.x + threadIdx.x;
    if (e < EE) atomicAdd(&g_deg[ei[EE + e]], 1);
}
// scan + dinv fused
__global__ void k_scan() {
    const int CH = (NN + 1023) / 1024;
    __shared__ int ss[1024];
    int t = threadIdx.x;
    int vals[CH];
    int base = t * CH;
    int loc = 0;
#pragma unroll
    for (int i = 0; i < CH; ++i) {
        int idx = base + i;
        int v = (idx < NN) ? g_deg[idx] : 0;
        if (idx < NN) g_dinv[idx] = rsqrtf((float)(v + 1));
        vals[i] = loc;
        loc += v;
    }
    ss[t] = loc;
    __syncthreads();
    for (int off = 1; off < 1024; off <<= 1) {
        int v = (t >= off) ? ss[t - off] : 0;
        __syncthreads();
        ss[t] += v;
        __syncthreads();
    }
    int pre = (t > 0) ? ss[t - 1] : 0;
#pragma unroll
    for (int i = 0; i < CH; ++i) {
        int idx = base + i;
        if (idx < NN) g_rowptr[idx] = pre + vals[i];
    }
    if (t == 1023) g_rowptr[NN] = ss[1023];
}
__global__ void k_fill(const int* __restrict__ ei) {
    int e = blockIdx.x * blockDim.x + threadIdx.x;
    if (e < EE) {
        int s = ei[e];
        int d = ei[EE + e];
        int pos = g_rowptr[d] + atomicAdd(&g_fill[d], 1);
        g_csrc[pos] = s;
        g_cw[pos] = g_dinv[s] * g_dinv[d];
    }
}

// ======================= W^T precompute (tf32 bits, permuted k) =======================
__global__ void k_wt(const float* __restrict__ W0, const float* __restrict__ W1,
                     const float* __restrict__ W2) {
    const float* Ws[3] = {W0, W1, W2};
    int l = blockIdx.y;
    int i = blockIdx.x * blockDim.x + threadIdx.x;   // output index (coalesced write)
    if (i < DD * DD) {
        int n = i >> 7;
        int kp = i & 127;
        int k = (kp & ~7) + ((kp & 7) >> 1) + ((kp & 1) << 2);  // inverse perm
        g_wt[l][i] = f2tf32(Ws[l][(size_t)k * DD + n]);
    }
}

// ======================= aggregation: xa = A_norm @ x =======================
__global__ void __launch_bounds__(256) k_agg(const float* __restrict__ xin,
                                             float* __restrict__ y) {
    int w = (blockIdx.x * blockDim.x + threadIdx.x) >> 5;
    int lane = threadIdx.x & 31;
    if (w >= NN) return;
    int col = lane * 4;

    float di = g_dinv[w];
    float sw = di * di;
    float4 acc = *(const float4*)(xin + (size_t)w * DD + col);
    acc.x *= sw; acc.y *= sw; acc.z *= sw; acc.w *= sw;

    int e0 = g_rowptr[w], e1 = g_rowptr[w + 1];
    for (int e = e0; e < e1; ++e) {
        int s = __ldg(&g_csrc[e]);
        float wt = __ldg(&g_cw[e]);
        float4 hs = *(const float4*)(xin + (size_t)s * DD + col);
        acc.x += wt * hs.x; acc.y += wt * hs.y;
        acc.z += wt * hs.z; acc.w += wt * hs.w;
    }
    *(float4*)(y + (size_t)w * DD + col) = acc;
}

// ======================= fused tf32 mma.sync GEMM + epilogue =======================
// TILE_M=64; 8 warps in 2(m) x 4(n); warp tile 32x32 = 2x4 m16n8k8 fragments.
#define TILE_M 64
#define SST 132
#define DYN_SMEM ((TILE_M + 128) * SST * 4)

__global__ void __launch_bounds__(256) k_gemm_fused(
    const float* __restrict__ A, const uint32_t* __restrict__ Wt,
    const float* __restrict__ bias, const float* __restrict__ gamma,
    const float* __restrict__ beta, const float* __restrict__ xres,
    float* __restrict__ y) {
    extern __shared__ float smem[];
    float* As = smem;                     // [64][SST], permuted k; reused for C
    float* Bs = smem + TILE_M * SST;      // [128][SST], permuted k (from g_wt)
    uint32_t* Asu = (uint32_t*)As;
    uint32_t* Bsu = (uint32_t*)Bs;
    __shared__ float s_b[128], s_g[128], s_be[128];

    int tid = threadIdx.x;
    int wid = tid >> 5;
    int lane = tid & 31;
    int m0 = blockIdx.x * TILE_M;

    if (tid < 128) { s_b[tid] = bias[tid]; s_g[tid] = gamma[tid]; s_be[tid] = beta[tid]; }

    // A tile [64][128] -> smem tf32, permuted k layout (scalar stores)
    for (int i = tid; i < TILE_M * 32; i += 256) {
        int m = i >> 5;
        int c = (i & 31) << 2;
        int gm = m0 + m;
        float4 v = (gm < NN) ? *(const float4*)(A + (size_t)gm * DD + c)
                             : make_float4(0.f, 0.f, 0.f, 0.f);
        uint32_t t0 = f2tf32(v.x), t1 = f2tf32(v.y), t2 = f2tf32(v.z), t3 = f2tf32(v.w);
        int base = m * SST + (c & ~7);
        int g0 = c & 7;                       // 0 or 4
        Asu[base + kperm(g0 + 0)] = t0;
        Asu[base + kperm(g0 + 1)] = t1;
        Asu[base + kperm(g0 + 2)] = t2;
        Asu[base + kperm(g0 + 3)] = t3;
    }
    // B tile: coalesced uint4 copy from pre-permuted Wt
    for (int i = tid; i < 128 * 32; i += 256) {
        int n = i >> 5;
        int c4 = (i & 31) << 2;
        *(uint4*)&Bsu[n * SST + c4] = *(const uint4*)&Wt[n * DD + c4];
    }
    __syncthreads();

    const int wm = (wid >> 2) * 32;       // 0 or 32
    const int wn = (wid & 3) * 32;        // 0,32,64,96
    const int qrow = lane >> 2;
    const int qcol = lane & 3;

    float c[2][4][4];
#pragma unroll
    for (int mt = 0; mt < 2; ++mt)
#pragma unroll
        for (int nt = 0; nt < 4; ++nt)
#pragma unroll
            for (int j = 0; j < 4; ++j) c[mt][nt][j] = 0.f;

#pragma unroll
    for (int ks = 0; ks < 16; ++ks) {
        int k0 = ks * 8;
        uint32_t a[2][4], b[4][2];
#pragma unroll
        for (int mt = 0; mt < 2; ++mt) {
            int r = wm + mt * 16 + qrow;
            uint2 lo = *(const uint2*)&Asu[r * SST + k0 + 2 * qcol];
            uint2 hi = *(const uint2*)&Asu[(r + 8) * SST + k0 + 2 * qcol];
            a[mt][0] = lo.x; a[mt][1] = hi.x; a[mt][2] = lo.y; a[mt][3] = hi.y;
        }
#pragma unroll
        for (int nt = 0; nt < 4; ++nt) {
            int n = wn + nt * 8 + qrow;
            uint2 bb = *(const uint2*)&Bsu[n * SST + k0 + 2 * qcol];
            b[nt][0] = bb.x; b[nt][1] = bb.y;
        }
#pragma unroll
        for (int mt = 0; mt < 2; ++mt)
#pragma unroll
            for (int nt = 0; nt < 4; ++nt)
                mma_tf32(c[mt][nt], a[mt], b[nt]);
    }

    // stage C into As (plain layout)
    __syncthreads();
#pragma unroll
    for (int mt = 0; mt < 2; ++mt) {
        int r = wm + mt * 16 + qrow;
#pragma unroll
        for (int nt = 0; nt < 4; ++nt) {
            int cc = wn + nt * 8 + qcol * 2;
            *(float2*)&As[r * SST + cc] = make_float2(c[mt][nt][0], c[mt][nt][1]);
            *(float2*)&As[(r + 8) * SST + cc] = make_float2(c[mt][nt][2], c[mt][nt][3]);
        }
    }
    __syncthreads();

    // epilogue: 8 rows per warp; lane holds 4 features
    int colb = lane * 4;
    float4 bv = *(const float4*)(s_b + colb);
    float4 gv = *(const float4*)(s_g + colb);
    float4 bev = *(const float4*)(s_be + colb);
#pragma unroll
    for (int rr = 0; rr < 8; ++rr) {
        int r = wid * 8 + rr;
        int row = m0 + r;
        if (row >= NN) break;
        float4 d = *(const float4*)&As[r * SST + colb];
        d.x += bv.x; d.y += bv.y; d.z += bv.z; d.w += bv.w;
        float s1 = d.x + d.y + d.z + d.w;
#pragma unroll
        for (int o = 16; o; o >>= 1) s1 += __shfl_xor_sync(0xffffffffu, s1, o);
        float mu = s1 * (1.f / 128.f);
        float d0 = d.x - mu, d1 = d.y - mu, d2 = d.z - mu, d3 = d.w - mu;
        float s2 = d0 * d0 + d1 * d1 + d2 * d2 + d3 * d3;
#pragma unroll
        for (int o = 16; o; o >>= 1) s2 += __shfl_xor_sync(0xffffffffu, s2, o);
        float rs = rsqrtf(s2 * (1.f / 128.f) + 1e-5f);

        float4 xv = *(const float4*)(xres + (size_t)row * DD + colb);
        float v0 = d0 * rs * gv.x + bev.x + xv.x;
        float v1 = d1 * rs * gv.y + bev.y + xv.y;
        float v2 = d2 * rs * gv.z + bev.z + xv.z;
        float v3 = d3 * rs * gv.w + bev.w + xv.w;
        v0 = v0 / (1.f + __expf(-v0));
        v1 = v1 / (1.f + __expf(-v1));
        v2 = v2 / (1.f + __expf(-v2));
        v3 = v3 / (1.f + __expf(-v3));
        *(float4*)(y + (size_t)row * DD + colb) = make_float4(v0, v1, v2, v3);
    }
}

// ======================= global mean pool =======================
__device__ __forceinline__ int lowerb(const int* __restrict__ a, int n, int key) {
    int lo = 0, hi = n;
    while (lo < hi) {
        int mid = (lo + hi) >> 1;
        if (a[mid] < key) lo = mid + 1; else hi = mid;
    }
    return lo;
}
__global__ void __launch_bounds__(128) k_pool(const float* __restrict__ x,
                                              const int* __restrict__ batch,
                                              float* __restrict__ out) {
    __shared__ int sl, sh;
    int g = blockIdx.x;
    if (threadIdx.x == 0) {
        sl = lowerb(batch, NN, g);
        sh = lowerb(batch, NN, g + 1);
    }
    __syncthreads();
    int lo = sl, hi = sh;
    int c = threadIdx.x;
    float sum = 0.f;
    for (int n = lo; n < hi; ++n) sum += x[(size_t)n * DD + c];
    out[g * DD + c] = sum / fmaxf((float)(hi - lo), 1.f);
}

// ======================= launch =======================
extern "C" void kernel_launch(void* const* d_in, const int* in_sizes, int n_in,
                              void* d_out, int out_size) {
    const float* x     = (const float*)d_in[0];
    const int*   ei    = (const int*)d_in[1];
    const int*   batch = (const int*)d_in[2];
    const float* W[3]  = {(const float*)d_in[3],  (const float*)d_in[7],  (const float*)d_in[11]};
    const float* b[3]  = {(const float*)d_in[4],  (const float*)d_in[8],  (const float*)d_in[12]};
    const float* g[3]  = {(const float*)d_in[5],  (const float*)d_in[9],  (const float*)d_in[13]};
    const float* be[3] = {(const float*)d_in[6],  (const float*)d_in[10], (const float*)d_in[14]};
    float* out = (float*)d_out;

    float *xa = nullptr, *y0 = nullptr, *y1 = nullptr;
    uint32_t* wt = nullptr;
    cudaGetSymbolAddress((void**)&xa, g_xa);
    cudaGetSymbolAddress((void**)&y0, g_y0);
    cudaGetSymbolAddress((void**)&y1, g_y1);
    cudaGetSymbolAddress((void**)&wt, g_wt);

    cudaFuncSetAttribute(k_gemm_fused, cudaFuncAttributeMaxDynamicSharedMemorySize, DYN_SMEM);

    k_init<<<(NN + 255) / 256, 256>>>();
    k_deg<<<(EE + 255) / 256, 256>>>(ei);
    k_scan<<<1, 1024>>>();
    k_fill<<<(EE + 255) / 256, 256>>>(ei);
    dim3 wtg((DD * DD + 255) / 256, 3);
    k_wt<<<wtg, 256>>>(W[0], W[1], W[2]);

    const int agg_blocks = (NN * 32 + 255) / 256;
    const int gemm_blocks = (NN + TILE_M - 1) / TILE_M;

    k_agg<<<agg_blocks, 256>>>(x, xa);
    k_gemm_fused<<<gemm_blocks, 256, DYN_SMEM>>>(xa, wt + 0 * DD * DD, b[0], g[0], be[0], x, y0);
    k_agg<<<agg_blocks, 256>>>(y0, xa);
    k_gemm_fused<<<gemm_blocks, 256, DYN_SMEM>>>(xa, wt + 1 * DD * DD, b[1], g[1], be[1], y0, y1);
    k_agg<<<agg_blocks, 256>>>(y1, xa);
    k_gemm_fused<<<gemm_blocks, 256, DYN_SMEM>>>(xa, wt + 2 * DD * DD, b[2], g[2], be[2], y1, y0);

    k_pool<<<GG, 128>>>(y0, batch, out);
}